// round 4
// baseline (speedup 1.0000x reference)
#include <cuda_runtime.h>

// Gaussian-splat over-compositing, N pixels x K gaussians, sm_103a.
// R4: spatial binning (32x32 tiles, counting sort) + per-(tile,k) activity
// mask + exact skip semantics:
//   - taken step: R3 exact scaled-numerator pair_step (passed at 2.5e-6)
//   - skipped run of m steps (e < 2^-34 for all lanes, pa unchanged):
//       u *= g^m  with g = pa*rcp(pa+eps) from the last taken step
//   - pixels with pa_final < 1e-4 recomputed with exact full loop (fallback)

#define MAXK   128
#define MAXN   (1 << 18)
#define TILE_W 32
#define TXD    16
#define NT     (TXD * TXD)       // 256 tiles
#define Q_CUT  34.0f             // skip if q upper bound < -Q_CUT (e < 2^-34)
#define PA_FB  1e-4f             // fallback threshold on final alpha

typedef unsigned long long u64;
typedef unsigned int u32;

// ---- device scratch (static, no allocation) ----
__device__ int d_hist[NT];
__device__ int d_cursor[NT];
__device__ int d_order[MAXN];
__device__ u32 d_tmask[NT][4];

// ---- packed f32x2 helpers ----
__device__ __forceinline__ u64 pack2(float a, float b) {
    u64 r; asm("mov.b64 %0, {%1, %2};" : "=l"(r) : "f"(a), "f"(b)); return r;
}
__device__ __forceinline__ void unpack2(u64 v, float& a, float& b) {
    asm("mov.b64 {%0, %1}, %2;" : "=f"(a), "=f"(b) : "l"(v));
}
__device__ __forceinline__ u64 fma2(u64 a, u64 b, u64 c) {
    u64 d; asm("fma.rn.f32x2 %0, %1, %2, %3;" : "=l"(d) : "l"(a), "l"(b), "l"(c)); return d;
}
__device__ __forceinline__ u64 add2(u64 a, u64 b) {
    u64 d; asm("add.rn.f32x2 %0, %1, %2;" : "=l"(d) : "l"(a), "l"(b)); return d;
}
__device__ __forceinline__ u64 mul2(u64 a, u64 b) {
    u64 d; asm("mul.rn.f32x2 %0, %1, %2;" : "=l"(d) : "l"(a), "l"(b)); return d;
}
__device__ __forceinline__ float ex2f_(float x) {
    float y; asm("ex2.approx.f32 %0, %1;" : "=f"(y) : "f"(x)); return y;
}
__device__ __forceinline__ float rcpf_(float x) {
    float y; asm("rcp.approx.f32 %0, %1;" : "=f"(y) : "f"(x)); return y;
}
__device__ __forceinline__ float lg2f_(float x) {
    float y; asm("lg2.approx.f32 %0, %1;" : "=f"(y) : "f"(x)); return y;
}

__device__ __forceinline__ int tile_of(float x, float y) {
    int tx = (int)(x * (1.0f / TILE_W)); tx = min(max(tx, 0), TXD - 1);
    int ty = (int)(y * (1.0f / TILE_W)); ty = min(max(ty, 0), TXD - 1);
    return ty * TXD + tx;
}

// ---- pair state: 2 pixels packed in f32x2 lanes ----
struct PairState {
    u64 x, y, x2, xy, y2;   // centered coords + monomials
    u64 u0, u1, u2;         // scaled color numerators
    u64 pa, omp, g;         // alpha, 1-alpha, carry factor pa/(pa+eps)
};

__device__ __forceinline__ void pair_init(PairState& S, float2 P0, float2 P1) {
    float ax = P0.x - 256.0f, ay = P0.y - 256.0f;
    float bx = P1.x - 256.0f, by = P1.y - 256.0f;
    S.x  = pack2(ax, bx);
    S.y  = pack2(ay, by);
    S.x2 = mul2(S.x, S.x);
    S.xy = mul2(S.x, S.y);
    S.y2 = mul2(S.y, S.y);
    S.u0 = S.u1 = S.u2 = 0ull;
    S.pa = 0ull; S.g = 0ull;
    S.omp = pack2(1.0f, 1.0f);
}

__device__ __forceinline__ void pair_step(PairState& S, const ulonglong2* __restrict__ g,
                                          int k, u64 EPS2, u64 NEG1) {
    ulonglong2 g0 = g[k * 5 + 0];   // {A2,  B22}
    ulonglong2 g1 = g[k * 5 + 1];   // {C2,  Dx2}
    ulonglong2 g2 = g[k * 5 + 2];   // {Ey2, F2}
    ulonglong2 g3 = g[k * 5 + 3];   // {c02, c12}
    ulonglong2 g4 = g[k * 5 + 4];   // {c22, pad}

    u64 t = fma2(g2.x, S.y, g2.y);       // Ey*y + F
    t = fma2(g1.y, S.x, t);              // + Dx*x
    t = fma2(g1.x, S.y2, t);             // + C*y2
    t = fma2(g0.y, S.xy, t);             // + B2*xy
    u64 q = fma2(g0.x, S.x2, t);         // + A*x2

    float qa, qb; unpack2(q, qa, qb);
    u64 e = pack2(ex2f_(qa), ex2f_(qb)); // alpha_k * gaussian

    u64 w = mul2(e, S.omp);
    S.u0 = fma2(S.u0, S.g, mul2(g3.x, w));   // u = u*g_prev + col*w
    S.u1 = fma2(S.u1, S.g, mul2(g3.y, w));
    S.u2 = fma2(S.u2, S.g, mul2(g4.x, w));

    u64 pan = add2(S.pa, w);
    S.omp = fma2(w, NEG1, S.omp);
    u64 d = add2(pan, EPS2);
    float da, db; unpack2(d, da, db);
    u64 r = pack2(rcpf_(da), rcpf_(db));
    S.g = mul2(pan, r);
    S.pa = pan;
}

// apply m skipped steps: u *= g^m (pa unchanged during skips)
__device__ __forceinline__ void pair_catchup(PairState& S, int m) {
    float g0, g1; unpack2(S.g, g0, g1);
    float fm = (float)m;
    float gm0 = ex2f_(fm * lg2f_(g0));   // g==1 -> exactly 1; g==0 -> 0
    float gm1 = ex2f_(fm * lg2f_(g1));
    u64 gm = pack2(gm0, gm1);
    S.u0 = mul2(S.u0, gm);
    S.u1 = mul2(S.u1, gm);
    S.u2 = mul2(S.u2, gm);
}

// ---- shared param prep (identical math to R3, which passed) ----
__device__ __forceinline__ void prep_params(float2* sp,
                                            const float* mu, const float* alpha,
                                            const float* color, const float* scales,
                                            const float* thetas, int K) {
    const float L2E = 1.44269504088896340736f;
    for (int k = threadIdx.x; k < K; k += blockDim.x) {
        float th = thetas[k];
        float c = cosf(th), s = sinf(th);
        float sx = fmaxf(scales[2 * k + 0], 0.1f);
        float sy = fmaxf(scales[2 * k + 1], 0.1f);
        float ix = 1.0f / (sx * sx);
        float iy = 1.0f / (sy * sy);
        float S00 = c * c * ix + s * s * iy;
        float S01 = c * s * (ix - iy);
        float S11 = s * s * ix + c * c * iy;
        float h = -0.5f * L2E;
        float A  = h * S00;
        float B2 = (2.0f * h) * S01;
        float C  = h * S11;
        float a  = fminf(fmaxf(alpha[k], 0.0f), 1.0f);
        float la = log2f(fmaxf(a, 1e-38f));
        float c0 = fminf(fmaxf(color[3 * k + 0], 0.0f), 255.0f);
        float c1 = fminf(fmaxf(color[3 * k + 1], 0.0f), 255.0f);
        float c2 = fminf(fmaxf(color[3 * k + 2], 0.0f), 255.0f);
        float mx = mu[2 * k + 0] - 256.0f;
        float my = mu[2 * k + 1] - 256.0f;
        float Dx = -(2.0f * A * mx + B2 * my);
        float Ey = -(B2 * mx + 2.0f * C * my);
        float F  = (A * mx * mx + B2 * mx * my + C * my * my) + la;
        float2* p = &sp[k * 10];
        p[0] = make_float2(A, A);   p[1] = make_float2(B2, B2);
        p[2] = make_float2(C, C);   p[3] = make_float2(Dx, Dx);
        p[4] = make_float2(Ey, Ey); p[5] = make_float2(F, F);
        p[6] = make_float2(c0, c0); p[7] = make_float2(c1, c1);
        p[8] = make_float2(c2, c2); p[9] = make_float2(0.0f, 0.0f);
    }
}

// ============================ binning kernels ============================

__global__ void k_zero() {
    int t = threadIdx.x;
    if (t < NT) d_hist[t] = 0;
}

__global__ __launch_bounds__(256) void k_hist(const float2* __restrict__ pos2, int n) {
    __shared__ int sh[NT];
    int tid = threadIdx.x;
    sh[tid] = 0;
    __syncthreads();
    int i = blockIdx.x * blockDim.x + tid;
    if (i < n) {
        float2 p = pos2[i];
        atomicAdd(&sh[tile_of(p.x, p.y)], 1);
    }
    __syncthreads();
    if (sh[tid]) atomicAdd(&d_hist[tid], sh[tid]);
}

__global__ void k_scan() {
    __shared__ int s[NT];
    int t = threadIdx.x;
    int v0 = d_hist[t];
    s[t] = v0;
    __syncthreads();
    for (int off = 1; off < NT; off <<= 1) {
        int v = (t >= off) ? s[t - off] : 0;
        __syncthreads();
        s[t] += v;
        __syncthreads();
    }
    d_cursor[t] = s[t] - v0;   // exclusive prefix
}

__global__ __launch_bounds__(256) void k_scatter(const float2* __restrict__ pos2, int n) {
    __shared__ int sh[NT];
    __shared__ int sbase[NT];
    int tid = threadIdx.x;
    sh[tid] = 0;
    __syncthreads();
    int i = blockIdx.x * blockDim.x + tid;
    int t = 0, lr = 0;
    if (i < n) {
        float2 p = pos2[i];
        t = tile_of(p.x, p.y);
        lr = atomicAdd(&sh[t], 1);
    }
    __syncthreads();
    sbase[tid] = sh[tid] ? atomicAdd(&d_cursor[tid], sh[tid]) : 0;
    __syncthreads();
    if (i < n) d_order[sbase[t] + lr] = i;
}

__global__ __launch_bounds__(256) void k_mask(const float* __restrict__ mu,
                                              const float* __restrict__ alpha,
                                              const float* __restrict__ scales,
                                              int K) {
    int id = blockIdx.x * blockDim.x + threadIdx.x;   // tile*4 + word
    if (id >= NT * 4) return;
    int tile = id >> 2, word = id & 3;
    int ty = tile / TXD, tx = tile % TXD;
    float rx0 = tx * (float)TILE_W, rx1 = rx0 + TILE_W;
    float ry0 = ty * (float)TILE_W, ry1 = ry0 + TILE_W;
    u32 bits = 0;
    for (int j = 0; j < 32; j++) {
        int k = word * 32 + j;
        if (k >= K) break;
        float mx = mu[2 * k + 0], my = mu[2 * k + 1];
        float dx = fmaxf(0.0f, fmaxf(rx0 - mx, mx - rx1));
        float dy = fmaxf(0.0f, fmaxf(ry0 - my, my - ry1));
        float d2 = dx * dx + dy * dy;
        float a  = fminf(fmaxf(alpha[k], 0.0f), 1.0f);
        float la = log2f(fmaxf(a, 1e-38f));
        float sx = fmaxf(scales[2 * k + 0], 0.1f);
        float sy = fmaxf(scales[2 * k + 1], 0.1f);
        float sm = fmaxf(sx, sy);
        // active iff upper bound la - 0.7213*d2/sm^2 >= -Q_CUT
        float rhs = (Q_CUT + la) * sm * sm;
        if (d2 * 0.72134752f < rhs) bits |= (1u << j);
    }
    d_tmask[tile][word] = bits;
}

// ============================ main kernel ============================

__global__ __launch_bounds__(128)
void k_main(const float* __restrict__ pos,
            const float* __restrict__ mu,
            const float* __restrict__ alpha,
            const float* __restrict__ color,
            const float* __restrict__ scales,
            const float* __restrict__ thetas,
            float4* __restrict__ out,
            int n, int K)
{
    __shared__ __align__(16) float2 sp[MAXK * 10];
    prep_params(sp, mu, alpha, color, scales, thetas, K);
    __syncthreads();

    // chunk permutation to spread hot tiles across SMs
    u32 g = gridDim.x;
    u32 mult = (g % 331u == 0u) ? 1u : 331u;
    u32 chunk = (blockIdx.x * mult) % g;

    int pairIdx = (int)chunk * blockDim.x + threadIdx.x;
    int i0g = pairIdx * 2, i1g = i0g + 1;
    bool v0 = (i0g < n), v1 = (i1g < n);

    int idx0 = 0, idx1 = 0;
    if (v0 && v1) {
        int2 o = ((const int2*)d_order)[pairIdx];
        idx0 = o.x; idx1 = o.y;
    } else if (v0) {
        idx0 = d_order[i0g];
    }

    const float2* pos2 = (const float2*)pos;
    float2 P0 = v0 ? pos2[idx0] : make_float2(0.0f, 0.0f);
    float2 P1 = v1 ? pos2[idx1] : make_float2(0.0f, 0.0f);

    int t0 = tile_of(P0.x, P0.y);
    int t1 = tile_of(P1.x, P1.y);

    u32 w0 = __reduce_or_sync(0xffffffffu, d_tmask[t0][0] | d_tmask[t1][0]);
    u32 w1 = __reduce_or_sync(0xffffffffu, d_tmask[t0][1] | d_tmask[t1][1]);
    u32 w2 = __reduce_or_sync(0xffffffffu, d_tmask[t0][2] | d_tmask[t1][2]);
    u32 w3 = __reduce_or_sync(0xffffffffu, d_tmask[t0][3] | d_tmask[t1][3]);

    PairState S;
    pair_init(S, P0, P1);

    const u64 EPS2 = pack2(1e-8f, 1e-8f);
    const u64 NEG1 = pack2(-1.0f, -1.0f);
    const ulonglong2* __restrict__ gp = (const ulonglong2*)sp;

    u32 words[4] = {w0, w1, w2, w3};
    int prevk = -1;
#pragma unroll
    for (int w = 0; w < 4; w++) {
        u32 bits = words[w];
        while (bits) {
            int b = __ffs(bits) - 1;
            bits &= bits - 1;
            int k = w * 32 + b;
            int m = k - prevk - 1;
            prevk = k;
            if (m > 0) pair_catchup(S, m);
            pair_step(S, gp, k, EPS2, NEG1);
        }
    }
    {
        int mtail = (K - 1) - prevk;
        if (mtail > 0) pair_catchup(S, mtail);
    }

    float pa0, pa1; unpack2(S.pa, pa0, pa1);

    // ---- fallback: exact full loop for low-alpha pixels (rare, warp-coherent) ----
    bool need0 = v0 && (pa0 < PA_FB);
    bool need1 = v1 && (pa1 < PA_FB);
    if (__any_sync(0xffffffffu, need0 || need1)) {
        PairState F;
        pair_init(F, P0, P1);
        for (int k = 0; k < K; k++) pair_step(F, gp, k, EPS2, NEG1);
        float fpa0, fpa1; unpack2(F.pa, fpa0, fpa1);
        float fu00, fu01; unpack2(F.u0, fu00, fu01);
        float fu10, fu11; unpack2(F.u1, fu10, fu11);
        float fu20, fu21; unpack2(F.u2, fu20, fu21);
        float u00, u01; unpack2(S.u0, u00, u01);
        float u10, u11; unpack2(S.u1, u10, u11);
        float u20, u21; unpack2(S.u2, u20, u21);
        if (need0) { pa0 = fpa0; u00 = fu00; u10 = fu10; u20 = fu20; }
        if (need1) { pa1 = fpa1; u01 = fu01; u11 = fu11; u21 = fu21; }
        S.u0 = pack2(u00, u01);
        S.u1 = pack2(u10, u11);
        S.u2 = pack2(u20, u21);
    }

    float u00, u01; unpack2(S.u0, u00, u01);
    float u10, u11; unpack2(S.u1, u10, u11);
    float u20, u21; unpack2(S.u2, u20, u21);

    if (v0) {
        float r = rcpf_(pa0 + 1e-8f);
        out[idx0] = make_float4(fminf(fmaxf(u00 * r, 0.0f), 255.0f),
                                fminf(fmaxf(u10 * r, 0.0f), 255.0f),
                                fminf(fmaxf(u20 * r, 0.0f), 255.0f),
                                fminf(fmaxf(pa0, 0.0f), 1.0f) * 255.0f);
    }
    if (v1) {
        float r = rcpf_(pa1 + 1e-8f);
        out[idx1] = make_float4(fminf(fmaxf(u01 * r, 0.0f), 255.0f),
                                fminf(fmaxf(u11 * r, 0.0f), 255.0f),
                                fminf(fmaxf(u21 * r, 0.0f), 255.0f),
                                fminf(fmaxf(pa1, 0.0f), 1.0f) * 255.0f);
    }
}

// ---- plain R3 kernel (fallback path for unexpected shapes) ----
__global__ __launch_bounds__(128)
void k_plain(const float* __restrict__ pos,
             const float* __restrict__ mu,
             const float* __restrict__ alpha,
             const float* __restrict__ color,
             const float* __restrict__ scales,
             const float* __restrict__ thetas,
             float4* __restrict__ out,
             int n, int K)
{
    __shared__ __align__(16) float2 sp[MAXK * 10];
    prep_params(sp, mu, alpha, color, scales, thetas, K);
    __syncthreads();

    int pairIdx = blockIdx.x * blockDim.x + threadIdx.x;
    int i0 = pairIdx * 2, i1 = i0 + 1;
    bool v0 = (i0 < n), v1 = (i1 < n);
    const float2* pos2 = (const float2*)pos;
    float2 P0 = v0 ? pos2[i0] : make_float2(0.0f, 0.0f);
    float2 P1 = v1 ? pos2[i1] : make_float2(0.0f, 0.0f);

    PairState S;
    pair_init(S, P0, P1);
    const u64 EPS2 = pack2(1e-8f, 1e-8f);
    const u64 NEG1 = pack2(-1.0f, -1.0f);
    const ulonglong2* __restrict__ gp = (const ulonglong2*)sp;
    for (int k = 0; k < K; k++) pair_step(S, gp, k, EPS2, NEG1);

    float pa0, pa1; unpack2(S.pa, pa0, pa1);
    float u00, u01; unpack2(S.u0, u00, u01);
    float u10, u11; unpack2(S.u1, u10, u11);
    float u20, u21; unpack2(S.u2, u20, u21);
    if (v0) {
        float r = rcpf_(pa0 + 1e-8f);
        out[i0] = make_float4(fminf(fmaxf(u00 * r, 0.0f), 255.0f),
                              fminf(fmaxf(u10 * r, 0.0f), 255.0f),
                              fminf(fmaxf(u20 * r, 0.0f), 255.0f),
                              fminf(fmaxf(pa0, 0.0f), 1.0f) * 255.0f);
    }
    if (v1) {
        float r = rcpf_(pa1 + 1e-8f);
        out[i1] = make_float4(fminf(fmaxf(u01 * r, 0.0f), 255.0f),
                              fminf(fmaxf(u11 * r, 0.0f), 255.0f),
                              fminf(fmaxf(u21 * r, 0.0f), 255.0f),
                              fminf(fmaxf(pa1, 0.0f), 1.0f) * 255.0f);
    }
}

extern "C" void kernel_launch(void* const* d_in, const int* in_sizes, int n_in,
                              void* d_out, int out_size)
{
    const float* pos    = (const float*)d_in[0];
    const float* mu     = (const float*)d_in[1];
    const float* alpha  = (const float*)d_in[2];
    const float* color  = (const float*)d_in[3];
    const float* scales = (const float*)d_in[4];
    const float* thetas = (const float*)d_in[5];

    int n = in_sizes[0] / 2;     // pixels
    int K = in_sizes[2];         // gaussians

    int pairs = (n + 1) / 2;
    int mainGrid = (pairs + 127) / 128;

    if (n > MAXN || K > MAXK || n < 1) {
        int Kc = K > MAXK ? MAXK : K;
        k_plain<<<mainGrid, 128>>>(pos, mu, alpha, color, scales, thetas,
                                   (float4*)d_out, n, Kc);
        return;
    }

    int binGrid = (n + 255) / 256;
    k_zero<<<1, 256>>>();
    k_hist<<<binGrid, 256>>>((const float2*)pos, n);
    k_scan<<<1, 256>>>();
    k_scatter<<<binGrid, 256>>>((const float2*)pos, n);
    k_mask<<<4, 256>>>(mu, alpha, scales, K);
    k_main<<<mainGrid, 128>>>(pos, mu, alpha, color, scales, thetas,
                              (float4*)d_out, n, K);
}

// round 5
// speedup vs baseline: 1.2463x; 1.2463x over previous
#include <cuda_runtime.h>

// Gaussian-splat over-compositing, N pixels x K gaussians, sm_103a.
// R5: tile binning (counting sort, low-depth atomics) + per-(tile,k) activity
// mask + exact skip semantics (u *= g^m catch-up), 4 pixels per main thread.

#define MAXK   128
#define MAXN   (1 << 18)
#define TILE_W 32
#define TXD    16
#define NT     (TXD * TXD)       // 256 tiles
#define Q_CUT  22.0f             // skip if q upper bound < -Q_CUT
#define PA_FB  1e-4f             // fallback threshold on final alpha
#define HB     128               // hist/scatter blocks (atomic chain depth)
#define PPB    8                 // pixels per thread in hist/scatter

typedef unsigned long long u64;
typedef unsigned int u32;

// ---- device scratch (static, no allocation) ----
__device__ int d_hist[NT];
__device__ int d_cursor[NT];
__device__ int d_order[MAXN];
__device__ u32 d_tmask[NT][4];

// ---- packed f32x2 helpers ----
__device__ __forceinline__ u64 pack2(float a, float b) {
    u64 r; asm("mov.b64 %0, {%1, %2};" : "=l"(r) : "f"(a), "f"(b)); return r;
}
__device__ __forceinline__ void unpack2(u64 v, float& a, float& b) {
    asm("mov.b64 {%0, %1}, %2;" : "=f"(a), "=f"(b) : "l"(v));
}
__device__ __forceinline__ u64 fma2(u64 a, u64 b, u64 c) {
    u64 d; asm("fma.rn.f32x2 %0, %1, %2, %3;" : "=l"(d) : "l"(a), "l"(b), "l"(c)); return d;
}
__device__ __forceinline__ u64 add2(u64 a, u64 b) {
    u64 d; asm("add.rn.f32x2 %0, %1, %2;" : "=l"(d) : "l"(a), "l"(b)); return d;
}
__device__ __forceinline__ u64 mul2(u64 a, u64 b) {
    u64 d; asm("mul.rn.f32x2 %0, %1, %2;" : "=l"(d) : "l"(a), "l"(b)); return d;
}
__device__ __forceinline__ float ex2f_(float x) {
    float y; asm("ex2.approx.f32 %0, %1;" : "=f"(y) : "f"(x)); return y;
}
__device__ __forceinline__ float rcpf_(float x) {
    float y; asm("rcp.approx.f32 %0, %1;" : "=f"(y) : "f"(x)); return y;
}
__device__ __forceinline__ float lg2f_(float x) {
    float y; asm("lg2.approx.f32 %0, %1;" : "=f"(y) : "f"(x)); return y;
}

__device__ __forceinline__ int tile_of(float x, float y) {
    int tx = (int)(x * (1.0f / TILE_W)); tx = min(max(tx, 0), TXD - 1);
    int ty = (int)(y * (1.0f / TILE_W)); ty = min(max(ty, 0), TXD - 1);
    return ty * TXD + tx;
}

// ---- pair state: 2 pixels packed in f32x2 lanes ----
struct PairState {
    u64 x, y, x2, xy, y2;   // centered coords + monomials
    u64 u0, u1, u2;         // scaled color numerators
    u64 pa, omp, g;         // alpha, 1-alpha, carry factor pa/(pa+eps)
};

__device__ __forceinline__ void pair_init(PairState& S, float2 P0, float2 P1) {
    float ax = P0.x - 256.0f, ay = P0.y - 256.0f;
    float bx = P1.x - 256.0f, by = P1.y - 256.0f;
    S.x  = pack2(ax, bx);
    S.y  = pack2(ay, by);
    S.x2 = mul2(S.x, S.x);
    S.xy = mul2(S.x, S.y);
    S.y2 = mul2(S.y, S.y);
    S.u0 = S.u1 = S.u2 = 0ull;
    S.pa = 0ull; S.g = 0ull;
    S.omp = pack2(1.0f, 1.0f);
}

__device__ __forceinline__ void pair_step(PairState& S,
                                          ulonglong2 g0, ulonglong2 g1,
                                          ulonglong2 g2, ulonglong2 g3,
                                          ulonglong2 g4,
                                          u64 EPS2, u64 NEG1) {
    u64 t = fma2(g2.x, S.y, g2.y);       // Ey*y + F
    t = fma2(g1.y, S.x, t);              // + Dx*x
    t = fma2(g1.x, S.y2, t);             // + C*y2
    t = fma2(g0.y, S.xy, t);             // + B2*xy
    u64 q = fma2(g0.x, S.x2, t);         // + A*x2

    float qa, qb; unpack2(q, qa, qb);
    u64 e = pack2(ex2f_(qa), ex2f_(qb)); // alpha_k * gaussian

    u64 w = mul2(e, S.omp);
    S.u0 = fma2(S.u0, S.g, mul2(g3.x, w));   // u = u*g_prev + col*w
    S.u1 = fma2(S.u1, S.g, mul2(g3.y, w));
    S.u2 = fma2(S.u2, S.g, mul2(g4.x, w));

    u64 pan = add2(S.pa, w);
    S.omp = fma2(w, NEG1, S.omp);
    u64 d = add2(pan, EPS2);
    float da, db; unpack2(d, da, db);
    u64 r = pack2(rcpf_(da), rcpf_(db));
    S.g = mul2(pan, r);
    S.pa = pan;
}

// apply m skipped steps: u *= g^m (pa unchanged during skips)
__device__ __forceinline__ void pair_catchup(PairState& S, float fm) {
    float g0, g1; unpack2(S.g, g0, g1);
    float gm0 = ex2f_(fm * lg2f_(g0));   // g==1 -> 1; g==0 -> 0
    float gm1 = ex2f_(fm * lg2f_(g1));
    u64 gm = pack2(gm0, gm1);
    S.u0 = mul2(S.u0, gm);
    S.u1 = mul2(S.u1, gm);
    S.u2 = mul2(S.u2, gm);
}

// ---- shared param prep (identical math to R3, which passed) ----
__device__ __forceinline__ void prep_params(float2* sp,
                                            const float* mu, const float* alpha,
                                            const float* color, const float* scales,
                                            const float* thetas, int K) {
    const float L2E = 1.44269504088896340736f;
    for (int k = threadIdx.x; k < K; k += blockDim.x) {
        float th = thetas[k];
        float c = cosf(th), s = sinf(th);
        float sx = fmaxf(scales[2 * k + 0], 0.1f);
        float sy = fmaxf(scales[2 * k + 1], 0.1f);
        float ix = 1.0f / (sx * sx);
        float iy = 1.0f / (sy * sy);
        float S00 = c * c * ix + s * s * iy;
        float S01 = c * s * (ix - iy);
        float S11 = s * s * ix + c * c * iy;
        float h = -0.5f * L2E;
        float A  = h * S00;
        float B2 = (2.0f * h) * S01;
        float C  = h * S11;
        float a  = fminf(fmaxf(alpha[k], 0.0f), 1.0f);
        float la = log2f(fmaxf(a, 1e-38f));
        float c0 = fminf(fmaxf(color[3 * k + 0], 0.0f), 255.0f);
        float c1 = fminf(fmaxf(color[3 * k + 1], 0.0f), 255.0f);
        float c2 = fminf(fmaxf(color[3 * k + 2], 0.0f), 255.0f);
        float mx = mu[2 * k + 0] - 256.0f;
        float my = mu[2 * k + 1] - 256.0f;
        float Dx = -(2.0f * A * mx + B2 * my);
        float Ey = -(B2 * mx + 2.0f * C * my);
        float F  = (A * mx * mx + B2 * mx * my + C * my * my) + la;
        float2* p = &sp[k * 10];
        p[0] = make_float2(A, A);   p[1] = make_float2(B2, B2);
        p[2] = make_float2(C, C);   p[3] = make_float2(Dx, Dx);
        p[4] = make_float2(Ey, Ey); p[5] = make_float2(F, F);
        p[6] = make_float2(c0, c0); p[7] = make_float2(c1, c1);
        p[8] = make_float2(c2, c2); p[9] = make_float2(0.0f, 0.0f);
    }
}

// ============================ binning kernels ============================

// blocks 0..3: per-(tile,k-word) activity mask.  block 4: zero d_hist.
__global__ __launch_bounds__(256)
void k_mask_zero(const float* __restrict__ mu,
                 const float* __restrict__ alpha,
                 const float* __restrict__ scales, int K) {
    if (blockIdx.x == 4) {
        if (threadIdx.x < NT) d_hist[threadIdx.x] = 0;
        return;
    }
    int id = blockIdx.x * blockDim.x + threadIdx.x;   // tile*4 + word
    if (id >= NT * 4) return;
    int tile = id >> 2, word = id & 3;
    int ty = tile / TXD, tx = tile % TXD;
    float rx0 = tx * (float)TILE_W, rx1 = rx0 + TILE_W;
    float ry0 = ty * (float)TILE_W, ry1 = ry0 + TILE_W;
    u32 bits = 0;
    for (int j = 0; j < 32; j++) {
        int k = word * 32 + j;
        if (k >= K) break;
        float mx = mu[2 * k + 0], my = mu[2 * k + 1];
        float dx = fmaxf(0.0f, fmaxf(rx0 - mx, mx - rx1));
        float dy = fmaxf(0.0f, fmaxf(ry0 - my, my - ry1));
        float d2 = dx * dx + dy * dy;
        float a  = fminf(fmaxf(alpha[k], 0.0f), 1.0f);
        float la = log2f(fmaxf(a, 1e-38f));
        float sx = fmaxf(scales[2 * k + 0], 0.1f);
        float sy = fmaxf(scales[2 * k + 1], 0.1f);
        float sm = fmaxf(sx, sy);
        float rhs = (Q_CUT + la) * sm * sm;   // active iff d2*ln2const < rhs
        if (d2 * 0.72134752f < rhs) bits |= (1u << j);
    }
    d_tmask[tile][word] = bits;
}

__global__ __launch_bounds__(256) void k_hist(const float2* __restrict__ pos2, int n) {
    __shared__ int sh[NT];
    int tid = threadIdx.x;
    sh[tid] = 0;
    __syncthreads();
    int base = blockIdx.x * (256 * PPB);
#pragma unroll
    for (int j = 0; j < PPB; j++) {
        int i = base + j * 256 + tid;
        if (i < n) {
            float2 p = pos2[i];
            atomicAdd(&sh[tile_of(p.x, p.y)], 1);
        }
    }
    __syncthreads();
    if (sh[tid]) atomicAdd(&d_hist[tid], sh[tid]);
}

__global__ void k_scan() {
    __shared__ int s[NT];
    int t = threadIdx.x;
    int v0 = d_hist[t];
    s[t] = v0;
    __syncthreads();
    for (int off = 1; off < NT; off <<= 1) {
        int v = (t >= off) ? s[t - off] : 0;
        __syncthreads();
        s[t] += v;
        __syncthreads();
    }
    d_cursor[t] = s[t] - v0;   // exclusive prefix
}

__global__ __launch_bounds__(256) void k_scatter(const float2* __restrict__ pos2, int n) {
    __shared__ int sh[NT];
    __shared__ int sbase[NT];
    int tid = threadIdx.x;
    sh[tid] = 0;
    __syncthreads();
    int base = blockIdx.x * (256 * PPB);
    int lt[PPB], lr[PPB];
#pragma unroll
    for (int j = 0; j < PPB; j++) {
        int i = base + j * 256 + tid;
        lt[j] = -1;
        if (i < n) {
            float2 p = pos2[i];
            int t = tile_of(p.x, p.y);
            lt[j] = t;
            lr[j] = atomicAdd(&sh[t], 1);
        }
    }
    __syncthreads();
    sbase[tid] = sh[tid] ? atomicAdd(&d_cursor[tid], sh[tid]) : 0;
    __syncthreads();
#pragma unroll
    for (int j = 0; j < PPB; j++) {
        int i = base + j * 256 + tid;
        if (lt[j] >= 0) d_order[sbase[lt[j]] + lr[j]] = i;
    }
}

// ============================ main kernel ============================

__global__ __launch_bounds__(128)
void k_main(const float* __restrict__ pos,
            const float* __restrict__ mu,
            const float* __restrict__ alpha,
            const float* __restrict__ color,
            const float* __restrict__ scales,
            const float* __restrict__ thetas,
            float4* __restrict__ out,
            int n, int K)
{
    __shared__ __align__(16) float2 sp[MAXK * 10];
    prep_params(sp, mu, alpha, color, scales, thetas, K);
    __syncthreads();

    // chunk permutation to spread hot tiles across SMs
    u32 g = gridDim.x;
    u32 mult = (g % 331u == 0u) ? 1u : 331u;
    u32 chunk = (blockIdx.x * mult) % g;

    // this block handles 256 pairs (512 pixels); 2 pairs per thread
    int pb = (int)chunk * 256;
    int pA = pb + threadIdx.x;
    int pB = pA + 128;

    int iA0 = pA * 2, iA1 = iA0 + 1, iB0 = pB * 2, iB1 = iB0 + 1;
    bool vA0 = (iA0 < n), vA1 = (iA1 < n), vB0 = (iB0 < n), vB1 = (iB1 < n);

    int idxA0 = 0, idxA1 = 0, idxB0 = 0, idxB1 = 0;
    if (vA1)      { int2 o = ((const int2*)d_order)[pA]; idxA0 = o.x; idxA1 = o.y; }
    else if (vA0) { idxA0 = d_order[iA0]; }
    if (vB1)      { int2 o = ((const int2*)d_order)[pB]; idxB0 = o.x; idxB1 = o.y; }
    else if (vB0) { idxB0 = d_order[iB0]; }

    const float2* pos2 = (const float2*)pos;
    float2 PA0 = vA0 ? pos2[idxA0] : make_float2(0.0f, 0.0f);
    float2 PA1 = vA1 ? pos2[idxA1] : make_float2(0.0f, 0.0f);
    float2 PB0 = vB0 ? pos2[idxB0] : make_float2(0.0f, 0.0f);
    float2 PB1 = vB1 ? pos2[idxB1] : make_float2(0.0f, 0.0f);

    int tA0 = tile_of(PA0.x, PA0.y), tA1 = tile_of(PA1.x, PA1.y);
    int tB0 = tile_of(PB0.x, PB0.y), tB1 = tile_of(PB1.x, PB1.y);

    u32 words[4];
#pragma unroll
    for (int w = 0; w < 4; w++) {
        u32 b = d_tmask[tA0][w] | d_tmask[tA1][w] | d_tmask[tB0][w] | d_tmask[tB1][w];
        words[w] = __reduce_or_sync(0xffffffffu, b);
    }

    PairState SA, SB;
    pair_init(SA, PA0, PA1);
    pair_init(SB, PB0, PB1);

    const u64 EPS2 = pack2(1e-8f, 1e-8f);
    const u64 NEG1 = pack2(-1.0f, -1.0f);
    const ulonglong2* __restrict__ gp = (const ulonglong2*)sp;

    int prevk = -1;
#pragma unroll
    for (int w = 0; w < 4; w++) {
        u32 bits = words[w];
        while (bits) {
            int b = __ffs(bits) - 1;
            bits &= bits - 1;
            int k = w * 32 + b;
            int m = k - prevk - 1;
            prevk = k;
            if (m > 0) {
                float fm = (float)m;
                pair_catchup(SA, fm);
                pair_catchup(SB, fm);
            }
            ulonglong2 g0 = gp[k * 5 + 0];
            ulonglong2 g1 = gp[k * 5 + 1];
            ulonglong2 g2 = gp[k * 5 + 2];
            ulonglong2 g3 = gp[k * 5 + 3];
            ulonglong2 g4 = gp[k * 5 + 4];
            pair_step(SA, g0, g1, g2, g3, g4, EPS2, NEG1);
            pair_step(SB, g0, g1, g2, g3, g4, EPS2, NEG1);
        }
    }
    {
        int mtail = (K - 1) - prevk;
        if (mtail > 0) {
            float fm = (float)mtail;
            pair_catchup(SA, fm);
            pair_catchup(SB, fm);
        }
    }

    float paA0, paA1; unpack2(SA.pa, paA0, paA1);
    float paB0, paB1; unpack2(SB.pa, paB0, paB1);

    // fallback: exact full loop for low-alpha pixels (rare, warp-coherent)
    bool needA = (vA0 && paA0 < PA_FB) || (vA1 && paA1 < PA_FB);
    bool needB = (vB0 && paB0 < PA_FB) || (vB1 && paB1 < PA_FB);
    if (__any_sync(0xffffffffu, needA)) {
        PairState F;
        pair_init(F, PA0, PA1);
        for (int k = 0; k < K; k++) {
            pair_step(F, gp[k*5+0], gp[k*5+1], gp[k*5+2], gp[k*5+3], gp[k*5+4],
                      EPS2, NEG1);
        }
        if (needA) { SA = F; unpack2(SA.pa, paA0, paA1); }
    }
    if (__any_sync(0xffffffffu, needB)) {
        PairState F;
        pair_init(F, PB0, PB1);
        for (int k = 0; k < K; k++) {
            pair_step(F, gp[k*5+0], gp[k*5+1], gp[k*5+2], gp[k*5+3], gp[k*5+4],
                      EPS2, NEG1);
        }
        if (needB) { SB = F; unpack2(SB.pa, paB0, paB1); }
    }

    float u00, u01, u10, u11, u20, u21;

    unpack2(SA.u0, u00, u01); unpack2(SA.u1, u10, u11); unpack2(SA.u2, u20, u21);
    if (vA0) {
        float r = rcpf_(paA0 + 1e-8f);
        out[idxA0] = make_float4(fminf(fmaxf(u00 * r, 0.0f), 255.0f),
                                 fminf(fmaxf(u10 * r, 0.0f), 255.0f),
                                 fminf(fmaxf(u20 * r, 0.0f), 255.0f),
                                 fminf(fmaxf(paA0, 0.0f), 1.0f) * 255.0f);
    }
    if (vA1) {
        float r = rcpf_(paA1 + 1e-8f);
        out[idxA1] = make_float4(fminf(fmaxf(u01 * r, 0.0f), 255.0f),
                                 fminf(fmaxf(u11 * r, 0.0f), 255.0f),
                                 fminf(fmaxf(u21 * r, 0.0f), 255.0f),
                                 fminf(fmaxf(paA1, 0.0f), 1.0f) * 255.0f);
    }
    unpack2(SB.u0, u00, u01); unpack2(SB.u1, u10, u11); unpack2(SB.u2, u20, u21);
    if (vB0) {
        float r = rcpf_(paB0 + 1e-8f);
        out[idxB0] = make_float4(fminf(fmaxf(u00 * r, 0.0f), 255.0f),
                                 fminf(fmaxf(u10 * r, 0.0f), 255.0f),
                                 fminf(fmaxf(u20 * r, 0.0f), 255.0f),
                                 fminf(fmaxf(paB0, 0.0f), 1.0f) * 255.0f);
    }
    if (vB1) {
        float r = rcpf_(paB1 + 1e-8f);
        out[idxB1] = make_float4(fminf(fmaxf(u01 * r, 0.0f), 255.0f),
                                 fminf(fmaxf(u11 * r, 0.0f), 255.0f),
                                 fminf(fmaxf(u21 * r, 0.0f), 255.0f),
                                 fminf(fmaxf(paB1, 0.0f), 1.0f) * 255.0f);
    }
}

// ---- plain full-loop kernel (fallback path for unexpected shapes) ----
__global__ __launch_bounds__(128)
void k_plain(const float* __restrict__ pos,
             const float* __restrict__ mu,
             const float* __restrict__ alpha,
             const float* __restrict__ color,
             const float* __restrict__ scales,
             const float* __restrict__ thetas,
             float4* __restrict__ out,
             int n, int K)
{
    __shared__ __align__(16) float2 sp[MAXK * 10];
    prep_params(sp, mu, alpha, color, scales, thetas, K);
    __syncthreads();

    int pairIdx = blockIdx.x * blockDim.x + threadIdx.x;
    int i0 = pairIdx * 2, i1 = i0 + 1;
    bool v0 = (i0 < n), v1 = (i1 < n);
    const float2* pos2 = (const float2*)pos;
    float2 P0 = v0 ? pos2[i0] : make_float2(0.0f, 0.0f);
    float2 P1 = v1 ? pos2[i1] : make_float2(0.0f, 0.0f);

    PairState S;
    pair_init(S, P0, P1);
    const u64 EPS2 = pack2(1e-8f, 1e-8f);
    const u64 NEG1 = pack2(-1.0f, -1.0f);
    const ulonglong2* __restrict__ gp = (const ulonglong2*)sp;
    for (int k = 0; k < K; k++)
        pair_step(S, gp[k*5+0], gp[k*5+1], gp[k*5+2], gp[k*5+3], gp[k*5+4],
                  EPS2, NEG1);

    float pa0, pa1; unpack2(S.pa, pa0, pa1);
    float u00, u01; unpack2(S.u0, u00, u01);
    float u10, u11; unpack2(S.u1, u10, u11);
    float u20, u21; unpack2(S.u2, u20, u21);
    if (v0) {
        float r = rcpf_(pa0 + 1e-8f);
        out[i0] = make_float4(fminf(fmaxf(u00 * r, 0.0f), 255.0f),
                              fminf(fmaxf(u10 * r, 0.0f), 255.0f),
                              fminf(fmaxf(u20 * r, 0.0f), 255.0f),
                              fminf(fmaxf(pa0, 0.0f), 1.0f) * 255.0f);
    }
    if (v1) {
        float r = rcpf_(pa1 + 1e-8f);
        out[i1] = make_float4(fminf(fmaxf(u01 * r, 0.0f), 255.0f),
                              fminf(fmaxf(u11 * r, 0.0f), 255.0f),
                              fminf(fmaxf(u21 * r, 0.0f), 255.0f),
                              fminf(fmaxf(pa1, 0.0f), 1.0f) * 255.0f);
    }
}

extern "C" void kernel_launch(void* const* d_in, const int* in_sizes, int n_in,
                              void* d_out, int out_size)
{
    const float* pos    = (const float*)d_in[0];
    const float* mu     = (const float*)d_in[1];
    const float* alpha  = (const float*)d_in[2];
    const float* color  = (const float*)d_in[3];
    const float* scales = (const float*)d_in[4];
    const float* thetas = (const float*)d_in[5];

    int n = in_sizes[0] / 2;     // pixels
    int K = in_sizes[2];         // gaussians

    if (n > MAXN || K > MAXK || n < 1) {
        int Kc = K > MAXK ? MAXK : K;
        int pairs = (n + 1) / 2;
        int grid = (pairs + 127) / 128;
        k_plain<<<grid, 128>>>(pos, mu, alpha, color, scales, thetas,
                               (float4*)d_out, n, Kc);
        return;
    }

    int pairs = (n + 1) / 2;
    int mainGrid = (pairs + 255) / 256;          // 256 pairs per block
    int hb = (n + 256 * PPB - 1) / (256 * PPB);  // <= HB
    if (hb > HB) hb = HB;

    k_mask_zero<<<5, 256>>>(mu, alpha, scales, K);
    k_hist<<<hb, 256>>>((const float2*)pos, n);
    k_scan<<<1, 256>>>();
    k_scatter<<<hb, 256>>>((const float2*)pos, n);
    k_main<<<mainGrid, 128>>>(pos, mu, alpha, color, scales, thetas,
                              (float4*)d_out, n, K);
}